// round 7
// baseline (speedup 1.0000x reference)
#include <cuda_runtime.h>

// SNN forward: T=1000, B=8192, I=9, H=96, O=3
// 16 lanes/batch (6 h each), 2 batches/warp, 4 warps/CTA, 5 CTAs/SM (<=102 regs).
// v = beta*mem1 + b1 - spk1 state fusion.
// w2 and b1 live in CTA smem (re-read per iter) to cut register pressure.
// Reduction split across iterations: xor8/xor4 at tail, xor2/xor1 + finalize at
// next iteration's head (overlapping loader LDG/STS and the layer-1 FFMA chain).

#define T_STEPS 1000
#define BATCHN  8192
#define BETA    0.92f

typedef unsigned long long u64;

static __device__ __forceinline__ u64 pk2(float lo, float hi) {
    u64 r; asm("mov.b64 %0,{%1,%2};" : "=l"(r) : "f"(lo), "f"(hi)); return r;
}
static __device__ __forceinline__ void upk2(u64 v, float& a, float& b) {
    asm("mov.b64 {%0,%1},%2;" : "=f"(a), "=f"(b) : "l"(v));
}
static __device__ __forceinline__ u64 ffma2(u64 a, u64 b, u64 c) {
    u64 d; asm("fma.rn.f32x2 %0,%1,%2,%3;" : "=l"(d) : "l"(a), "l"(b), "l"(c)); return d;
}
static __device__ __forceinline__ u64 fadd2(u64 a, u64 b) {
    u64 d; asm("add.rn.f32x2 %0,%1,%2;" : "=l"(d) : "l"(a), "l"(b)); return d;
}
static __device__ __forceinline__ u64 fmul2(u64 a, u64 b) {
    u64 d; asm("mul.rn.f32x2 %0,%1,%2;" : "=l"(d) : "l"(a), "l"(b)); return d;
}
static __device__ __forceinline__ void lds128(u64& a, u64& b, const u64* p) {
    asm("ld.shared.v2.u64 {%0,%1},[%2];" : "=l"(a), "=l"(b) : "l"(__cvta_generic_to_shared(p)));
}

__global__ void __launch_bounds__(128, 5) snn_kernel(
    const float* __restrict__ x,
    const float* __restrict__ W1,
    const float* __restrict__ b1,
    const float* __restrict__ W2,
    const float* __restrict__ b2,
    float* __restrict__ out)
{
    const int lane = threadIdx.x & 31;
    const int warp = threadIdx.x >> 5;
    const int gw   = blockIdx.x * 4 + warp;
    const int grp  = lane >> 4;                  // batch slot within warp
    const int hl   = lane & 15;                  // hidden slice 0..15
    const int hb   = hl * 6;
    const int b    = gw * 2 + grp;

    // x staging ring: [warp][buf3][batchslot][10] (80B rows, 16B aligned)
    __shared__ __align__(16) u64 xs[4][3][2][10];
    // CTA-shared per-hl weights: w2 rows (9 u64, padded to 10) and b1 (3 u64 -> 4)
    __shared__ __align__(16) u64 w2s[16][10];
    __shared__ __align__(16) u64 b1s[16][4];

    // one-time CTA init of w2s/b1s
    if (threadIdx.x < 16) {
        int h0 = threadIdx.x * 6;
        #pragma unroll
        for (int o = 0; o < 3; o++)
            #pragma unroll
            for (int j = 0; j < 3; j++)
                w2s[threadIdx.x][o * 3 + j] =
                    pk2(W2[o * 96 + h0 + 2*j], W2[o * 96 + h0 + 2*j + 1]);
        #pragma unroll
        for (int j = 0; j < 3; j++)
            b1s[threadIdx.x][j] = pk2(b1[h0 + 2*j], b1[h0 + 2*j + 1]);
    }

    // ---- w1 in registers ----
    u64 w1p[3][9];
    #pragma unroll
    for (int j = 0; j < 3; j++)
        #pragma unroll
        for (int i = 0; i < 9; i++)
            w1p[j][i] = pk2(W1[(hb + 2*j) * 9 + i], W1[(hb + 2*j + 1) * 9 + i]);

    const u64 BET2 = pk2(BETA, BETA);

    // ---- finalize lane roles ----
    const int  oc        = (hl >> 2) > 2 ? 2 : (hl >> 2);
    const bool fin_store = ((hl & 3) < 2) && (hl < 12);
    const bool is_spk    = (hl & 3) == 0;
    const float bias     = b2[oc];

    float* optr = (is_spk ? out : out + (size_t)T_STEPS * BATCHN * 3)
                  + (size_t)b * 3 + oc;

    // ---- state:  v = beta*mem1 + b1 - spk1 ----
    __syncthreads();                         // w2s/b1s ready
    u64 v0 = b1s[hl][0], v1 = b1s[hl][1], v2 = b1s[hl][2];
    float m2 = 0.f, ns = 0.f;
    float pp = 0.f;                          // half-reduced layer-2 sum (prev step)

    // ---- x loader pipeline (lanes 0..17 load 2 batches x 9 inputs) ----
    const bool loader = lane < 18;
    const int  gl = lane / 9, il = lane - gl * 9;
    const float* xb = x + (size_t)(gw * 2 + gl) * 9 + il;
    const size_t xstr = (size_t)BATCHN * 9;

    float r = loader ? xb[0] : 0.f;
    if (loader) xs[warp][0][gl][il] = pk2(r, r);            // buf0 = x(0)
    r = loader ? xb[xstr] : 0.f;                            // in flight: x(1)
    __syncwarp();

    int bcur = 0, bnext = 1, bnn = 2;
    #pragma unroll 3
    for (int t = 0; t < T_STEPS; t++) {
        // ---- stage x(t+1), launch load of x(t+2) ----
        if (loader) xs[warp][bnext][gl][il] = pk2(r, r);
        {
            int tn = (t + 2 < T_STEPS) ? (t + 2) : (T_STEPS - 1);
            r = loader ? xb[(size_t)tn * xstr] : 0.f;
        }

        // ---- head: complete previous step's reduction + finalize + store ----
        if (t) {
            float sv = pp;
            sv += __shfl_xor_sync(0xffffffffu, sv, 2);
            sv += __shfl_xor_sync(0xffffffffu, sv, 1);
            float mm = fmaf(BETA, m2, bias - sv) + ns;
            m2 = mm;
            float spkv = (mm > 1.0f) ? 1.0f : 0.0f;
            ns = (mm > 1.0f) ? -1.0f : 0.0f;
            if (fin_store) __stcs(optr, is_spk ? spkv : mm);
            optr += 3 * BATCHN;
        }
        __syncwarp();

        // ---- load x pairs ----
        const u64* xrow = xs[warp][bcur][grp];
        u64 xp[9];
        lds128(xp[0], xp[1], xrow + 0);
        lds128(xp[2], xp[3], xrow + 2);
        lds128(xp[4], xp[5], xrow + 4);
        lds128(xp[6], xp[7], xrow + 6);
        xp[8] = xrow[8];

        // ---- layer 1: a = v + x@W1^T ----
        u64 a0 = v0, a1 = v1, a2 = v2;
        #pragma unroll
        for (int i = 0; i < 9; i++) {
            a0 = ffma2(w1p[0][i], xp[i], a0);
            a1 = ffma2(w1p[1][i], xp[i], a1);
            a2 = ffma2(w1p[2][i], xp[i], a2);
        }

        // ---- spikes (negated) + state v = beta*a + (q + b1) ----
        float f0, f1;
        upk2(a0, f0, f1);
        u64 q0 = pk2((f0 > 1.0f) ? -1.0f : 0.0f, (f1 > 1.0f) ? -1.0f : 0.0f);
        upk2(a1, f0, f1);
        u64 q1 = pk2((f0 > 1.0f) ? -1.0f : 0.0f, (f1 > 1.0f) ? -1.0f : 0.0f);
        upk2(a2, f0, f1);
        u64 q2 = pk2((f0 > 1.0f) ? -1.0f : 0.0f, (f1 > 1.0f) ? -1.0f : 0.0f);
        {
            u64 bb0, bb1c, bb2c, bpad;
            lds128(bb0, bb1c, &b1s[hl][0]);
            bb2c = b1s[hl][2]; (void)bpad;
            v0 = ffma2(BET2, a0, fadd2(q0, bb0));
            v1 = ffma2(BET2, a1, fadd2(q1, bb1c));
            v2 = ffma2(BET2, a2, fadd2(q2, bb2c));
        }

        // ---- layer-2 partials: c_o = sum(-spk * w2[o]) (w2 from smem) ----
        u64 wr[9];
        {
            const u64* wrow = w2s[hl];
            lds128(wr[0], wr[1], wrow + 0);
            lds128(wr[2], wr[3], wrow + 2);
            lds128(wr[4], wr[5], wrow + 4);
            lds128(wr[6], wr[7], wrow + 6);
            wr[8] = wrow[8];
        }
        u64 c0 = fmul2(q0, wr[0]); c0 = ffma2(q1, wr[1], c0); c0 = ffma2(q2, wr[2], c0);
        u64 c1 = fmul2(q0, wr[3]); c1 = ffma2(q1, wr[4], c1); c1 = ffma2(q2, wr[5], c1);
        u64 c2 = fmul2(q0, wr[6]); c2 = ffma2(q1, wr[7], c2); c2 = ffma2(q2, wr[8], c2);
        float s0, s1, s2, ta, tb;
        upk2(c0, ta, tb); s0 = ta + tb;
        upk2(c1, ta, tb); s1 = ta + tb;
        upk2(c2, ta, tb); s2 = ta + tb;

        // ---- tail: first two reduction levels + select ----
        s0 += __shfl_xor_sync(0xffffffffu, s0, 8);
        s1 += __shfl_xor_sync(0xffffffffu, s1, 8);
        s2 += __shfl_xor_sync(0xffffffffu, s2, 8);
        s0 += __shfl_xor_sync(0xffffffffu, s0, 4);
        s1 += __shfl_xor_sync(0xffffffffu, s1, 4);
        s2 += __shfl_xor_sync(0xffffffffu, s2, 4);
        pp = (oc == 0) ? s0 : ((oc == 1) ? s1 : s2);

        int tmp = bcur; bcur = bnext; bnext = bnn; bnn = tmp;
    }

    // epilogue: timestep T-1
    {
        float sv = pp;
        sv += __shfl_xor_sync(0xffffffffu, sv, 2);
        sv += __shfl_xor_sync(0xffffffffu, sv, 1);
        float mm = fmaf(BETA, m2, bias - sv) + ns;
        if (fin_store) {
            float spkv = (mm > 1.0f) ? 1.0f : 0.0f;
            __stcs(optr, is_spk ? spkv : mm);
        }
    }
}

extern "C" void kernel_launch(void* const* d_in, const int* in_sizes, int n_in,
                              void* d_out, int out_size) {
    const float* x  = (const float*)d_in[0];
    const float* W1 = (const float*)d_in[1];
    const float* b1 = (const float*)d_in[2];
    const float* W2 = (const float*)d_in[3];
    const float* b2 = (const float*)d_in[4];
    float* out = (float*)d_out;

    snn_kernel<<<1024, 128>>>(x, W1, b1, W2, b2, out);
}

// round 8
// speedup vs baseline: 1.3703x; 1.3703x over previous
#include <cuda_runtime.h>

// SNN forward: T=1000, B=8192, I=9, H=96, O=3
// 4 batches/warp (2 independent batch-sets => 2x ILP per warp), 16 weight lanes,
// weights in registers (w1:54, w2:18, b1:6 regs shared across both sets).
// v = beta*mem1 + b1 - spk1 state fusion; reduction split across iterations.

#define T_STEPS 1000
#define BATCHN  8192
#define BETA    0.92f

typedef unsigned long long u64;

static __device__ __forceinline__ u64 pk2(float lo, float hi) {
    u64 r; asm("mov.b64 %0,{%1,%2};" : "=l"(r) : "f"(lo), "f"(hi)); return r;
}
static __device__ __forceinline__ void upk2(u64 v, float& a, float& b) {
    asm("mov.b64 {%0,%1},%2;" : "=f"(a), "=f"(b) : "l"(v));
}
static __device__ __forceinline__ u64 ffma2(u64 a, u64 b, u64 c) {
    u64 d; asm("fma.rn.f32x2 %0,%1,%2,%3;" : "=l"(d) : "l"(a), "l"(b), "l"(c)); return d;
}
static __device__ __forceinline__ u64 fadd2(u64 a, u64 b) {
    u64 d; asm("add.rn.f32x2 %0,%1,%2;" : "=l"(d) : "l"(a), "l"(b)); return d;
}
static __device__ __forceinline__ u64 fmul2(u64 a, u64 b) {
    u64 d; asm("mul.rn.f32x2 %0,%1,%2;" : "=l"(d) : "l"(a), "l"(b)); return d;
}
static __device__ __forceinline__ void lds128(u64& a, u64& b, const u64* p) {
    asm("ld.shared.v2.u64 {%0,%1},[%2];" : "=l"(a), "=l"(b) : "l"(__cvta_generic_to_shared(p)));
}

__global__ void __launch_bounds__(128, 3) snn_kernel(
    const float* __restrict__ x,
    const float* __restrict__ W1,
    const float* __restrict__ b1,
    const float* __restrict__ W2,
    const float* __restrict__ b2,
    float* __restrict__ out)
{
    const int lane = threadIdx.x & 31;
    const int warp = threadIdx.x >> 5;
    const int gw   = blockIdx.x * 4 + warp;
    const int grp  = lane >> 4;                  // batch slot within set (0/1)
    const int hl   = lane & 15;                  // hidden slice 0..15
    const int hb   = hl * 6;
    const int bA   = gw * 4 + grp;               // set-0 batch; set-1 = bA + 2

    // x staging ring: [warp][buf3][4 slots x 10 u64] (slot rows 16B aligned)
    __shared__ __align__(16) u64 xs[4][3][40];

    // ---- weights in registers (shared by both batch sets) ----
    u64 w1p[3][9];
    #pragma unroll
    for (int j = 0; j < 3; j++)
        #pragma unroll
        for (int i = 0; i < 9; i++)
            w1p[j][i] = pk2(W1[(hb + 2*j) * 9 + i], W1[(hb + 2*j + 1) * 9 + i]);

    u64 w2p[3][3];
    #pragma unroll
    for (int o = 0; o < 3; o++)
        #pragma unroll
        for (int j = 0; j < 3; j++)
            w2p[o][j] = pk2(W2[o * 96 + hb + 2*j], W2[o * 96 + hb + 2*j + 1]);

    u64 b1p[3];
    #pragma unroll
    for (int j = 0; j < 3; j++) b1p[j] = pk2(b1[hb + 2*j], b1[hb + 2*j + 1]);

    const u64 BET2 = pk2(BETA, BETA);

    // ---- finalize lane roles ----
    const int  oc        = (hl >> 2) > 2 ? 2 : (hl >> 2);
    const bool fin_store = ((hl & 3) < 2) && (hl < 12);
    const bool is_spk    = (hl & 3) == 0;
    const float bias     = b2[oc];

    float* optr = (is_spk ? out : out + (size_t)T_STEPS * BATCHN * 3)
                  + (size_t)bA * 3 + oc;         // set-1 target = optr + 6

    // ---- state per set:  v = beta*mem1 + b1 - spk1 ----
    u64 vA0 = b1p[0], vA1 = b1p[1], vA2 = b1p[2];
    u64 vB0 = b1p[0], vB1 = b1p[1], vB2 = b1p[2];
    float m2A = 0.f, nsA = 0.f, ppA = 0.f;
    float m2B = 0.f, nsB = 0.f, ppB = 0.f;

    // ---- x loaders: 36 contiguous floats per warp-step ----
    // value idx -> (slot = idx/9, i = idx%9); smem offset slot*10 + i
    const int  idx0 = lane;
    const int  off0 = (idx0 / 9) * 10 + idx0 % 9;
    const bool l2   = lane < 4;
    const int  idx1 = 32 + lane;
    const int  off1 = (idx1 / 9) * 10 + idx1 % 9;
    const float* p0 = x + (size_t)gw * 36 + idx0;
    const float* p1 = x + (size_t)gw * 36 + idx1;
    const size_t xstr = (size_t)BATCHN * 9;

    float r0 = p0[0];
    float r1 = l2 ? p1[0] : 0.f;
    xs[warp][0][off0] = pk2(r0, r0);
    if (l2) xs[warp][0][off1] = pk2(r1, r1);
    r0 = p0[xstr];
    r1 = l2 ? p1[xstr] : 0.f;
    __syncwarp();

    int bcur = 0, bnext = 1, bnn = 2;
    #pragma unroll 3
    for (int t = 0; t < T_STEPS; t++) {
        // ---- stage x(t+1), launch load of x(t+2) ----
        xs[warp][bnext][off0] = pk2(r0, r0);
        if (l2) xs[warp][bnext][off1] = pk2(r1, r1);
        {
            int tn = (t + 2 < T_STEPS) ? (t + 2) : (T_STEPS - 1);
            r0 = p0[(size_t)tn * xstr];
            r1 = l2 ? p1[(size_t)tn * xstr] : 0.f;
        }

        // ---- head: finish previous step's reductions + finalize + store ----
        if (t) {
            float svA = ppA, svB = ppB;
            svA += __shfl_xor_sync(0xffffffffu, svA, 2);
            svB += __shfl_xor_sync(0xffffffffu, svB, 2);
            svA += __shfl_xor_sync(0xffffffffu, svA, 1);
            svB += __shfl_xor_sync(0xffffffffu, svB, 1);
            float mmA = fmaf(BETA, m2A, bias - svA) + nsA;  m2A = mmA;
            float mmB = fmaf(BETA, m2B, bias - svB) + nsB;  m2B = mmB;
            nsA = (mmA > 1.0f) ? -1.0f : 0.0f;
            nsB = (mmB > 1.0f) ? -1.0f : 0.0f;
            if (fin_store) {
                __stcs(optr,     is_spk ? ((mmA > 1.0f) ? 1.0f : 0.0f) : mmA);
                __stcs(optr + 6, is_spk ? ((mmB > 1.0f) ? 1.0f : 0.0f) : mmB);
            }
            optr += 3 * BATCHN;
        }
        __syncwarp();

        float sA0, sA1, sA2, sB0, sB1, sB2;

        // ======== batch set A ========
        {
            const u64* xrow = xs[warp][bcur] + grp * 10;
            u64 xp[9];
            lds128(xp[0], xp[1], xrow + 0);
            lds128(xp[2], xp[3], xrow + 2);
            lds128(xp[4], xp[5], xrow + 4);
            lds128(xp[6], xp[7], xrow + 6);
            xp[8] = xrow[8];

            u64 a0 = vA0, a1 = vA1, a2 = vA2;
            #pragma unroll
            for (int i = 0; i < 9; i++) {
                a0 = ffma2(w1p[0][i], xp[i], a0);
                a1 = ffma2(w1p[1][i], xp[i], a1);
                a2 = ffma2(w1p[2][i], xp[i], a2);
            }
            float f0, f1;
            upk2(a0, f0, f1);
            u64 q0 = pk2((f0 > 1.0f) ? -1.0f : 0.0f, (f1 > 1.0f) ? -1.0f : 0.0f);
            upk2(a1, f0, f1);
            u64 q1 = pk2((f0 > 1.0f) ? -1.0f : 0.0f, (f1 > 1.0f) ? -1.0f : 0.0f);
            upk2(a2, f0, f1);
            u64 q2 = pk2((f0 > 1.0f) ? -1.0f : 0.0f, (f1 > 1.0f) ? -1.0f : 0.0f);
            vA0 = ffma2(BET2, a0, fadd2(q0, b1p[0]));
            vA1 = ffma2(BET2, a1, fadd2(q1, b1p[1]));
            vA2 = ffma2(BET2, a2, fadd2(q2, b1p[2]));

            u64 c0 = fmul2(q0, w2p[0][0]); c0 = ffma2(q1, w2p[0][1], c0); c0 = ffma2(q2, w2p[0][2], c0);
            u64 c1 = fmul2(q0, w2p[1][0]); c1 = ffma2(q1, w2p[1][1], c1); c1 = ffma2(q2, w2p[1][2], c1);
            u64 c2 = fmul2(q0, w2p[2][0]); c2 = ffma2(q1, w2p[2][1], c2); c2 = ffma2(q2, w2p[2][2], c2);
            float ta, tb;
            upk2(c0, ta, tb); sA0 = ta + tb;
            upk2(c1, ta, tb); sA1 = ta + tb;
            upk2(c2, ta, tb); sA2 = ta + tb;
        }

        // ======== batch set B ========
        {
            const u64* xrow = xs[warp][bcur] + (grp + 2) * 10;
            u64 xp[9];
            lds128(xp[0], xp[1], xrow + 0);
            lds128(xp[2], xp[3], xrow + 2);
            lds128(xp[4], xp[5], xrow + 4);
            lds128(xp[6], xp[7], xrow + 6);
            xp[8] = xrow[8];

            u64 a0 = vB0, a1 = vB1, a2 = vB2;
            #pragma unroll
            for (int i = 0; i < 9; i++) {
                a0 = ffma2(w1p[0][i], xp[i], a0);
                a1 = ffma2(w1p[1][i], xp[i], a1);
                a2 = ffma2(w1p[2][i], xp[i], a2);
            }
            float f0, f1;
            upk2(a0, f0, f1);
            u64 q0 = pk2((f0 > 1.0f) ? -1.0f : 0.0f, (f1 > 1.0f) ? -1.0f : 0.0f);
            upk2(a1, f0, f1);
            u64 q1 = pk2((f0 > 1.0f) ? -1.0f : 0.0f, (f1 > 1.0f) ? -1.0f : 0.0f);
            upk2(a2, f0, f1);
            u64 q2 = pk2((f0 > 1.0f) ? -1.0f : 0.0f, (f1 > 1.0f) ? -1.0f : 0.0f);
            vB0 = ffma2(BET2, a0, fadd2(q0, b1p[0]));
            vB1 = ffma2(BET2, a1, fadd2(q1, b1p[1]));
            vB2 = ffma2(BET2, a2, fadd2(q2, b1p[2]));

            u64 c0 = fmul2(q0, w2p[0][0]); c0 = ffma2(q1, w2p[0][1], c0); c0 = ffma2(q2, w2p[0][2], c0);
            u64 c1 = fmul2(q0, w2p[1][0]); c1 = ffma2(q1, w2p[1][1], c1); c1 = ffma2(q2, w2p[1][2], c1);
            u64 c2 = fmul2(q0, w2p[2][0]); c2 = ffma2(q1, w2p[2][1], c2); c2 = ffma2(q2, w2p[2][2], c2);
            float ta, tb;
            upk2(c0, ta, tb); sB0 = ta + tb;
            upk2(c1, ta, tb); sB1 = ta + tb;
            upk2(c2, ta, tb); sB2 = ta + tb;
        }

        // ---- tails interleaved: xor8 then xor4, six independent values ----
        sA0 += __shfl_xor_sync(0xffffffffu, sA0, 8);
        sA1 += __shfl_xor_sync(0xffffffffu, sA1, 8);
        sA2 += __shfl_xor_sync(0xffffffffu, sA2, 8);
        sB0 += __shfl_xor_sync(0xffffffffu, sB0, 8);
        sB1 += __shfl_xor_sync(0xffffffffu, sB1, 8);
        sB2 += __shfl_xor_sync(0xffffffffu, sB2, 8);
        sA0 += __shfl_xor_sync(0xffffffffu, sA0, 4);
        sA1 += __shfl_xor_sync(0xffffffffu, sA1, 4);
        sA2 += __shfl_xor_sync(0xffffffffu, sA2, 4);
        sB0 += __shfl_xor_sync(0xffffffffu, sB0, 4);
        sB1 += __shfl_xor_sync(0xffffffffu, sB1, 4);
        sB2 += __shfl_xor_sync(0xffffffffu, sB2, 4);
        ppA = (oc == 0) ? sA0 : ((oc == 1) ? sA1 : sA2);
        ppB = (oc == 0) ? sB0 : ((oc == 1) ? sB1 : sB2);

        int tmp = bcur; bcur = bnext; bnext = bnn; bnn = tmp;
    }

    // ---- epilogue: timestep T-1 for both sets ----
    {
        float svA = ppA, svB = ppB;
        svA += __shfl_xor_sync(0xffffffffu, svA, 2);
        svB += __shfl_xor_sync(0xffffffffu, svB, 2);
        svA += __shfl_xor_sync(0xffffffffu, svA, 1);
        svB += __shfl_xor_sync(0xffffffffu, svB, 1);
        float mmA = fmaf(BETA, m2A, bias - svA) + nsA;
        float mmB = fmaf(BETA, m2B, bias - svB) + nsB;
        if (fin_store) {
            __stcs(optr,     is_spk ? ((mmA > 1.0f) ? 1.0f : 0.0f) : mmA);
            __stcs(optr + 6, is_spk ? ((mmB > 1.0f) ? 1.0f : 0.0f) : mmB);
        }
    }
}

extern "C" void kernel_launch(void* const* d_in, const int* in_sizes, int n_in,
                              void* d_out, int out_size) {
    const float* x  = (const float*)d_in[0];
    const float* W1 = (const float*)d_in[1];
    const float* b1 = (const float*)d_in[2];
    const float* W2 = (const float*)d_in[3];
    const float* b2 = (const float*)d_in[4];
    float* out = (float*)d_out;

    // 8192 batches / (4 per warp * 4 warps) = 512 CTAs
    snn_kernel<<<512, 128>>>(x, W1, b1, W2, b2, out);
}

// round 9
// speedup vs baseline: 1.7861x; 1.3035x over previous
#include <cuda_runtime.h>

// SNN forward: T=1000, B=8192, I=9, H=96, O=3
// 4 batches/warp (2 independent batch-sets = 2x ILP), 16 weight lanes.
// CTA = 64 threads (2 warps), grid = 1024, 7 CTAs/SM -> SINGLE WAVE.
// v = beta*mem1 + b1 - spk1 state fusion; reduction split across iterations.

#define T_STEPS 1000
#define BATCHN  8192
#define BETA    0.92f

typedef unsigned long long u64;

static __device__ __forceinline__ u64 pk2(float lo, float hi) {
    u64 r; asm("mov.b64 %0,{%1,%2};" : "=l"(r) : "f"(lo), "f"(hi)); return r;
}
static __device__ __forceinline__ void upk2(u64 v, float& a, float& b) {
    asm("mov.b64 {%0,%1},%2;" : "=f"(a), "=f"(b) : "l"(v));
}
static __device__ __forceinline__ u64 ffma2(u64 a, u64 b, u64 c) {
    u64 d; asm("fma.rn.f32x2 %0,%1,%2,%3;" : "=l"(d) : "l"(a), "l"(b), "l"(c)); return d;
}
static __device__ __forceinline__ u64 fadd2(u64 a, u64 b) {
    u64 d; asm("add.rn.f32x2 %0,%1,%2;" : "=l"(d) : "l"(a), "l"(b)); return d;
}
static __device__ __forceinline__ u64 fmul2(u64 a, u64 b) {
    u64 d; asm("mul.rn.f32x2 %0,%1,%2;" : "=l"(d) : "l"(a), "l"(b)); return d;
}
static __device__ __forceinline__ void lds128(u64& a, u64& b, const u64* p) {
    asm("ld.shared.v2.u64 {%0,%1},[%2];" : "=l"(a), "=l"(b) : "l"(__cvta_generic_to_shared(p)));
}

__global__ void __launch_bounds__(64, 7) snn_kernel(
    const float* __restrict__ x,
    const float* __restrict__ W1,
    const float* __restrict__ b1,
    const float* __restrict__ W2,
    const float* __restrict__ b2,
    float* __restrict__ out)
{
    const int lane = threadIdx.x & 31;
    const int warp = threadIdx.x >> 5;
    const int gw   = blockIdx.x * 2 + warp;
    const int grp  = lane >> 4;                  // batch slot within set (0/1)
    const int hl   = lane & 15;                  // hidden slice 0..15
    const int hb   = hl * 6;
    const int bA   = gw * 4 + grp;               // set-0 batch; set-1 = bA + 2

    // x staging ring: [warp][buf3][4 slots x 10 u64] (slot rows 16B aligned)
    __shared__ __align__(16) u64 xs[2][3][40];

    // ---- weights in registers (shared by both batch sets) ----
    u64 w1p[3][9];
    #pragma unroll
    for (int j = 0; j < 3; j++)
        #pragma unroll
        for (int i = 0; i < 9; i++)
            w1p[j][i] = pk2(W1[(hb + 2*j) * 9 + i], W1[(hb + 2*j + 1) * 9 + i]);

    u64 w2p[3][3];
    #pragma unroll
    for (int o = 0; o < 3; o++)
        #pragma unroll
        for (int j = 0; j < 3; j++)
            w2p[o][j] = pk2(W2[o * 96 + hb + 2*j], W2[o * 96 + hb + 2*j + 1]);

    u64 b1p[3];
    #pragma unroll
    for (int j = 0; j < 3; j++) b1p[j] = pk2(b1[hb + 2*j], b1[hb + 2*j + 1]);

    const u64 BET2 = pk2(BETA, BETA);

    // ---- finalize lane roles ----
    const int  oc        = (hl >> 2) > 2 ? 2 : (hl >> 2);
    const bool fin_store = ((hl & 3) < 2) && (hl < 12);
    const bool is_spk    = (hl & 3) == 0;
    const float bias     = b2[oc];

    float* optr = (is_spk ? out : out + (size_t)T_STEPS * BATCHN * 3)
                  + (size_t)bA * 3 + oc;         // set-1 target = optr + 6

    // ---- state per set:  v = beta*mem1 + b1 - spk1 ----
    u64 vA0 = b1p[0], vA1 = b1p[1], vA2 = b1p[2];
    u64 vB0 = b1p[0], vB1 = b1p[1], vB2 = b1p[2];
    float m2A = 0.f, nsA = 0.f, ppA = 0.f;
    float m2B = 0.f, nsB = 0.f, ppB = 0.f;

    // ---- x loaders: 36 contiguous floats per warp-step ----
    const int  idx0 = lane;
    const int  off0 = (idx0 / 9) * 10 + idx0 % 9;
    const bool l2   = lane < 4;
    const int  idx1 = 32 + lane;
    const int  off1 = (idx1 / 9) * 10 + idx1 % 9;
    const float* p0 = x + (size_t)gw * 36 + idx0;
    const float* p1 = x + (size_t)gw * 36 + idx1;
    const size_t xstr = (size_t)BATCHN * 9;

    float r0 = p0[0];
    float r1 = l2 ? p1[0] : 0.f;
    xs[warp][0][off0] = pk2(r0, r0);
    if (l2) xs[warp][0][off1] = pk2(r1, r1);
    r0 = p0[xstr];
    r1 = l2 ? p1[xstr] : 0.f;
    __syncwarp();

    int bcur = 0, bnext = 1, bnn = 2;
    #pragma unroll 3
    for (int t = 0; t < T_STEPS; t++) {
        // ---- stage x(t+1), launch load of x(t+2) ----
        xs[warp][bnext][off0] = pk2(r0, r0);
        if (l2) xs[warp][bnext][off1] = pk2(r1, r1);
        {
            int tn = (t + 2 < T_STEPS) ? (t + 2) : (T_STEPS - 1);
            r0 = p0[(size_t)tn * xstr];
            r1 = l2 ? p1[(size_t)tn * xstr] : 0.f;
        }

        // ---- head: finish previous step's reductions + finalize + store ----
        if (t) {
            float svA = ppA, svB = ppB;
            svA += __shfl_xor_sync(0xffffffffu, svA, 2);
            svB += __shfl_xor_sync(0xffffffffu, svB, 2);
            svA += __shfl_xor_sync(0xffffffffu, svA, 1);
            svB += __shfl_xor_sync(0xffffffffu, svB, 1);
            float mmA = fmaf(BETA, m2A, bias - svA) + nsA;  m2A = mmA;
            float mmB = fmaf(BETA, m2B, bias - svB) + nsB;  m2B = mmB;
            nsA = (mmA > 1.0f) ? -1.0f : 0.0f;
            nsB = (mmB > 1.0f) ? -1.0f : 0.0f;
            if (fin_store) {
                __stcs(optr,     is_spk ? ((mmA > 1.0f) ? 1.0f : 0.0f) : mmA);
                __stcs(optr + 6, is_spk ? ((mmB > 1.0f) ? 1.0f : 0.0f) : mmB);
            }
            optr += 3 * BATCHN;
        }
        __syncwarp();

        float sA0, sA1, sA2, sB0, sB1, sB2;

        // ======== batch set A ========
        {
            const u64* xrow = xs[warp][bcur] + grp * 10;
            u64 xp[9];
            lds128(xp[0], xp[1], xrow + 0);
            lds128(xp[2], xp[3], xrow + 2);
            lds128(xp[4], xp[5], xrow + 4);
            lds128(xp[6], xp[7], xrow + 6);
            xp[8] = xrow[8];

            u64 a0 = vA0, a1 = vA1, a2 = vA2;
            #pragma unroll
            for (int i = 0; i < 9; i++) {
                a0 = ffma2(w1p[0][i], xp[i], a0);
                a1 = ffma2(w1p[1][i], xp[i], a1);
                a2 = ffma2(w1p[2][i], xp[i], a2);
            }
            float f0, f1;
            upk2(a0, f0, f1);
            u64 q0 = pk2((f0 > 1.0f) ? -1.0f : 0.0f, (f1 > 1.0f) ? -1.0f : 0.0f);
            upk2(a1, f0, f1);
            u64 q1 = pk2((f0 > 1.0f) ? -1.0f : 0.0f, (f1 > 1.0f) ? -1.0f : 0.0f);
            upk2(a2, f0, f1);
            u64 q2 = pk2((f0 > 1.0f) ? -1.0f : 0.0f, (f1 > 1.0f) ? -1.0f : 0.0f);
            vA0 = ffma2(BET2, a0, fadd2(q0, b1p[0]));
            vA1 = ffma2(BET2, a1, fadd2(q1, b1p[1]));
            vA2 = ffma2(BET2, a2, fadd2(q2, b1p[2]));

            u64 c0 = fmul2(q0, w2p[0][0]); c0 = ffma2(q1, w2p[0][1], c0); c0 = ffma2(q2, w2p[0][2], c0);
            u64 c1 = fmul2(q0, w2p[1][0]); c1 = ffma2(q1, w2p[1][1], c1); c1 = ffma2(q2, w2p[1][2], c1);
            u64 c2 = fmul2(q0, w2p[2][0]); c2 = ffma2(q1, w2p[2][1], c2); c2 = ffma2(q2, w2p[2][2], c2);
            float ta, tb;
            upk2(c0, ta, tb); sA0 = ta + tb;
            upk2(c1, ta, tb); sA1 = ta + tb;
            upk2(c2, ta, tb); sA2 = ta + tb;
        }

        // ======== batch set B ========
        {
            const u64* xrow = xs[warp][bcur] + (grp + 2) * 10;
            u64 xp[9];
            lds128(xp[0], xp[1], xrow + 0);
            lds128(xp[2], xp[3], xrow + 2);
            lds128(xp[4], xp[5], xrow + 4);
            lds128(xp[6], xp[7], xrow + 6);
            xp[8] = xrow[8];

            u64 a0 = vB0, a1 = vB1, a2 = vB2;
            #pragma unroll
            for (int i = 0; i < 9; i++) {
                a0 = ffma2(w1p[0][i], xp[i], a0);
                a1 = ffma2(w1p[1][i], xp[i], a1);
                a2 = ffma2(w1p[2][i], xp[i], a2);
            }
            float f0, f1;
            upk2(a0, f0, f1);
            u64 q0 = pk2((f0 > 1.0f) ? -1.0f : 0.0f, (f1 > 1.0f) ? -1.0f : 0.0f);
            upk2(a1, f0, f1);
            u64 q1 = pk2((f0 > 1.0f) ? -1.0f : 0.0f, (f1 > 1.0f) ? -1.0f : 0.0f);
            upk2(a2, f0, f1);
            u64 q2 = pk2((f0 > 1.0f) ? -1.0f : 0.0f, (f1 > 1.0f) ? -1.0f : 0.0f);
            vB0 = ffma2(BET2, a0, fadd2(q0, b1p[0]));
            vB1 = ffma2(BET2, a1, fadd2(q1, b1p[1]));
            vB2 = ffma2(BET2, a2, fadd2(q2, b1p[2]));

            u64 c0 = fmul2(q0, w2p[0][0]); c0 = ffma2(q1, w2p[0][1], c0); c0 = ffma2(q2, w2p[0][2], c0);
            u64 c1 = fmul2(q0, w2p[1][0]); c1 = ffma2(q1, w2p[1][1], c1); c1 = ffma2(q2, w2p[1][2], c1);
            u64 c2 = fmul2(q0, w2p[2][0]); c2 = ffma2(q1, w2p[2][1], c2); c2 = ffma2(q2, w2p[2][2], c2);
            float ta, tb;
            upk2(c0, ta, tb); sB0 = ta + tb;
            upk2(c1, ta, tb); sB1 = ta + tb;
            upk2(c2, ta, tb); sB2 = ta + tb;
        }

        // ---- tails interleaved: xor8 then xor4, six independent values ----
        sA0 += __shfl_xor_sync(0xffffffffu, sA0, 8);
        sA1 += __shfl_xor_sync(0xffffffffu, sA1, 8);
        sA2 += __shfl_xor_sync(0xffffffffu, sA2, 8);
        sB0 += __shfl_xor_sync(0xffffffffu, sB0, 8);
        sB1 += __shfl_xor_sync(0xffffffffu, sB1, 8);
        sB2 += __shfl_xor_sync(0xffffffffu, sB2, 8);
        sA0 += __shfl_xor_sync(0xffffffffu, sA0, 4);
        sA1 += __shfl_xor_sync(0xffffffffu, sA1, 4);
        sA2 += __shfl_xor_sync(0xffffffffu, sA2, 4);
        sB0 += __shfl_xor_sync(0xffffffffu, sB0, 4);
        sB1 += __shfl_xor_sync(0xffffffffu, sB1, 4);
        sB2 += __shfl_xor_sync(0xffffffffu, sB2, 4);
        ppA = (oc == 0) ? sA0 : ((oc == 1) ? sA1 : sA2);
        ppB = (oc == 0) ? sB0 : ((oc == 1) ? sB1 : sB2);

        int tmp = bcur; bcur = bnext; bnext = bnn; bnn = tmp;
    }

    // ---- epilogue: timestep T-1 for both sets ----
    {
        float svA = ppA, svB = ppB;
        svA += __shfl_xor_sync(0xffffffffu, svA, 2);
        svB += __shfl_xor_sync(0xffffffffu, svB, 2);
        svA += __shfl_xor_sync(0xffffffffu, svA, 1);
        svB += __shfl_xor_sync(0xffffffffu, svB, 1);
        float mmA = fmaf(BETA, m2A, bias - svA) + nsA;
        float mmB = fmaf(BETA, m2B, bias - svB) + nsB;
        if (fin_store) {
            __stcs(optr,     is_spk ? ((mmA > 1.0f) ? 1.0f : 0.0f) : mmA);
            __stcs(optr + 6, is_spk ? ((mmB > 1.0f) ? 1.0f : 0.0f) : mmB);
        }
    }
}

extern "C" void kernel_launch(void* const* d_in, const int* in_sizes, int n_in,
                              void* d_out, int out_size) {
    const float* x  = (const float*)d_in[0];
    const float* W1 = (const float*)d_in[1];
    const float* b1 = (const float*)d_in[2];
    const float* W2 = (const float*)d_in[3];
    const float* b2 = (const float*)d_in[4];
    float* out = (float*)d_out;

    // 8192 batches / (4 per warp * 2 warps) = 1024 CTAs of 64 threads
    // 7 CTAs/SM * 148 SMs = 1036 >= 1024 -> single wave
    snn_kernel<<<1024, 64>>>(x, W1, b1, W2, b2, out);
}